// round 10
// baseline (speedup 1.0000x reference)
#include <cuda_runtime.h>
#include <cstdint>
#include <cstddef>

// out[t, n*16+f] = relu(bias[f] + sum_{j=0..31} x[t-2j-1, n] * w_pn[j][f])
// w_pn = per-filter l2-normalized relu(weights); rows t-2j-1 < 0 contribute 0.
//
// R7 winner + two surgical changes:
//  - warp tile 8t x 8f (f-split across warp pairs): weight LDS per j: 8 -> 2
//    (LDS.128), 16 FMAs per LDS byte-wise -> crossbar/issue relief.
//  - register double-buffered weights: step j prefetches j+1's 4 pairs ->
//    LDS->use distance = one full j-step (~70cyc) >> 29cyc LDS latency.
// x path unchanged: group-of-4 lag batching with 8-row LDG prefetch, __stcs
// streaming stores. Thread tile: 1 n x 8 t x 8 f, f-paired f32x2 accumulators.

#define T_DIM 2048
#define N_DIM 4096
#define L_DIM 32
#define F_DIM 16
#define OUTW  (N_DIM * F_DIM)

using ull = unsigned long long;

__device__ __forceinline__ ull dup2(float v) {
    ull r;
    unsigned u = __float_as_uint(v);
    asm("mov.b64 %0, {%1, %1};" : "=l"(r) : "r"(u));
    return r;
}

__device__ __forceinline__ void fma2(ull& d, ull a, ull b) {
    asm("fma.rn.f32x2 %0, %1, %2, %0;" : "+l"(d) : "l"(a), "l"(b));
}

__device__ __forceinline__ float2 unpack2(ull v) {
    float2 r;
    asm("mov.b64 {%0, %1}, %2;" : "=f"(r.x), "=f"(r.y) : "l"(v));
    return r;
}

// x[t0 + off, n]: off is a compile-time literal -> [base + imm] addressing.
template<bool GUARD>
__device__ __forceinline__ float ldrow(const float* __restrict__ p, int t0, int off) {
    if (GUARD && (t0 + off < 0)) return 0.0f;
    return __ldg(p + (ptrdiff_t)off * N_DIM);
}

// Warp tile: 1 n-lane x 8 consecutive t x 8 filters (fg*8 .. fg*8+7).
template<bool GUARD>
__device__ __forceinline__ void compute_tile(
    const float* __restrict__ xt,    // x + t0*N + n
    float* __restrict__ op,          // out + t0*OUTW + n*16 + fg*8
    const float* __restrict__ sw,    // smem normalized weights [32][16]
    const float* __restrict__ sb,    // smem biases [16]
    int t0, int fg)
{
    // acc[t][q] = {out[t0+t, fg*8+2q], out[t0+t, fg*8+2q+1]} pre-relu
    ull acc[8][4];
    {
        const ull* sb2 = reinterpret_cast<const ull*>(sb) + fg * 4;
#pragma unroll
        for (int q = 0; q < 4; ++q) {
            ull b = sb2[q];
#pragma unroll
            for (int t = 0; t < 8; ++t) acc[t][q] = b;
        }
    }

    // weight rows as 16B chunks: row j = 4 x ulonglong2, this warp uses 2.
    const ulonglong2* wsrc = reinterpret_cast<const ulonglong2*>(sw) + fg * 2;

    // double-buffered weight pairs; wq[j&1] holds lag j's 4 filter-pairs
    ull wq[2][4];
    {
        ulonglong2 a = wsrc[0];
        ulonglong2 b = wsrc[1];
        wq[0][0] = a.x; wq[0][1] = a.y; wq[0][2] = b.x; wq[0][3] = b.y;
    }

    // Window entering group g (j0=4g): win[k] = x[t0 - 2*j0 - 7 + k], k=0..13.
    // Lag j0+d (d=0..3) needs rows win[6-2d .. 13-2d].
    float win[14];
#pragma unroll
    for (int k = 0; k < 14; ++k)
        win[k] = ldrow<GUARD>(xt, t0, -7 + k);

#pragma unroll
    for (int g = 0; g < 8; ++g) {
        // batch-prefetch next group's 8 rows (MLP=8, distance ~4 j-steps)
        float nbuf[8];
        if (g < 7) {
#pragma unroll
            for (int k = 0; k < 8; ++k)
                nbuf[k] = ldrow<GUARD>(xt, t0, -8 * g - 15 + k);
        }

#pragma unroll
        for (int d = 0; d < 4; ++d) {
            const int j   = 4 * g + d;
            const int cur = j & 1;
            const int nxt = cur ^ 1;

            // prefetch next lag's weights into the alternate buffer
            if (j < L_DIM - 1) {
                ulonglong2 a = wsrc[(j + 1) * 4];
                ulonglong2 b = wsrc[(j + 1) * 4 + 1];
                wq[nxt][0] = a.x; wq[nxt][1] = a.y;
                wq[nxt][2] = b.x; wq[nxt][3] = b.y;
            }

            ull xd[8];
#pragma unroll
            for (int t = 0; t < 8; ++t)
                xd[t] = dup2(win[6 - 2 * d + t]);

#pragma unroll
            for (int q = 0; q < 4; ++q) {
                ull w = wq[cur][q];
#pragma unroll
                for (int t = 0; t < 8; ++t)
                    fma2(acc[t][q], xd[t], w);
            }
        }

        // shift window down 8 rows; new base = old base - 8
        if (g < 7) {
#pragma unroll
            for (int k = 13; k >= 8; --k) win[k] = win[k - 8];
#pragma unroll
            for (int k = 0; k < 8; ++k) win[k] = nbuf[k];
        }
    }

    // relu + streaming stores: 8 contiguous floats per t = 2x STG.128.
    // Adjacent q-pairs are adjacent filters -> direct float4 assembly.
#pragma unroll
    for (int t = 0; t < 8; ++t) {
        float4* dst = reinterpret_cast<float4*>(op + (size_t)t * OUTW);
        float2 a0 = unpack2(acc[t][0]);
        float2 a1 = unpack2(acc[t][1]);
        float2 a2 = unpack2(acc[t][2]);
        float2 a3 = unpack2(acc[t][3]);
        float4 v0, v1;
        v0.x = fmaxf(a0.x, 0.0f); v0.y = fmaxf(a0.y, 0.0f);
        v0.z = fmaxf(a1.x, 0.0f); v0.w = fmaxf(a1.y, 0.0f);
        v1.x = fmaxf(a2.x, 0.0f); v1.y = fmaxf(a2.y, 0.0f);
        v1.z = fmaxf(a3.x, 0.0f); v1.w = fmaxf(a3.y, 0.0f);
        __stcs(dst + 0, v0);
        __stcs(dst + 1, v1);
    }
}

__global__ void __launch_bounds__(256, 2)
tlayer_kernel(const float* __restrict__ x,
              const float* __restrict__ W,
              const float* __restrict__ B,
              float* __restrict__ out)
{
    __shared__ __align__(16) float sw[L_DIM * F_DIM];  // normalized weights [j][f]
    __shared__ __align__(16) float sb[F_DIM];

    const int tid = threadIdx.x;

    // weight prep: relu + per-filter l2 normalize (matches reference)
    if (tid < F_DIM) {
        float ss = 0.0f;
        for (int j = 0; j < L_DIM; ++j) {
            float wv = fmaxf(__ldg(W + j * F_DIM + tid), 0.0f);
            ss += wv * wv;
        }
        float inv = rsqrtf(fmaxf(ss, 1e-12f));
        for (int j = 0; j < L_DIM; ++j) {
            sw[j * F_DIM + tid] = fmaxf(__ldg(W + j * F_DIM + tid), 0.0f) * inv;
        }
        sb[tid] = __ldg(B + tid);
    }
    __syncthreads();

    const int lane = tid & 31;
    const int warp = tid >> 5;
    const int tg   = warp >> 1;      // 4 t-groups of 8
    const int fg   = warp & 1;       // 2 filter-halves

    const int n  = blockIdx.x * 32 + lane;        // 128 n-blocks
    const int t0 = blockIdx.y * 32 + tg * 8;      // 64 t-blocks, 32 t per block

    const float* xt = x + (size_t)t0 * N_DIM + n;
    float*       op = out + (size_t)t0 * OUTW + (size_t)n * F_DIM + fg * 8;

    // deepest row touched is t0 - 63; guard only the first t-blocks
    if (t0 >= 63) {
        compute_tile<false>(xt, op, sw, sb, t0, fg);
    } else {
        compute_tile<true>(xt, op, sw, sb, t0, fg);
    }
}

extern "C" void kernel_launch(void* const* d_in, const int* in_sizes, int n_in,
                              void* d_out, int out_size) {
    (void)in_sizes; (void)n_in; (void)out_size;
    const float* x = (const float*)d_in[0];   // [2048, 4096]
    const float* W = (const float*)d_in[1];   // [32, 16]
    const float* B = (const float*)d_in[2];   // [16]
    float* out = (float*)d_out;               // [2048, 65536]

    dim3 grid(N_DIM / 32, T_DIM / 32);        // (128, 64)
    tlayer_kernel<<<grid, 256>>>(x, W, B, out);
}

// round 11
// speedup vs baseline: 1.0049x; 1.0049x over previous
#include <cuda_runtime.h>
#include <cstdint>
#include <cstddef>

// out[t, n*16+f] = relu(bias[f] + sum_{j=0..31} x[t-2j-1, n] * w_pn[j][f])
// w_pn = per-filter l2-normalized relu(weights); rows t-2j-1 < 0 contribute 0.
//
// R7 winner + two surgical changes:
//  - warp tile 8t x 8f (f-split across warp pairs): weight LDS per j: 8 -> 2
//    (LDS.128), 16 FMAs per LDS byte-wise -> crossbar/issue relief.
//  - register double-buffered weights: step j prefetches j+1's 4 pairs ->
//    LDS->use distance = one full j-step (~70cyc) >> 29cyc LDS latency.
// x path unchanged: group-of-4 lag batching with 8-row LDG prefetch, __stcs
// streaming stores. Thread tile: 1 n x 8 t x 8 f, f-paired f32x2 accumulators.

#define T_DIM 2048
#define N_DIM 4096
#define L_DIM 32
#define F_DIM 16
#define OUTW  (N_DIM * F_DIM)

using ull = unsigned long long;

__device__ __forceinline__ ull dup2(float v) {
    ull r;
    unsigned u = __float_as_uint(v);
    asm("mov.b64 %0, {%1, %1};" : "=l"(r) : "r"(u));
    return r;
}

__device__ __forceinline__ void fma2(ull& d, ull a, ull b) {
    asm("fma.rn.f32x2 %0, %1, %2, %0;" : "+l"(d) : "l"(a), "l"(b));
}

__device__ __forceinline__ float2 unpack2(ull v) {
    float2 r;
    asm("mov.b64 {%0, %1}, %2;" : "=f"(r.x), "=f"(r.y) : "l"(v));
    return r;
}

// x[t0 + off, n]: off is a compile-time literal -> [base + imm] addressing.
template<bool GUARD>
__device__ __forceinline__ float ldrow(const float* __restrict__ p, int t0, int off) {
    if (GUARD && (t0 + off < 0)) return 0.0f;
    return __ldg(p + (ptrdiff_t)off * N_DIM);
}

// Warp tile: 1 n-lane x 8 consecutive t x 8 filters (fg*8 .. fg*8+7).
template<bool GUARD>
__device__ __forceinline__ void compute_tile(
    const float* __restrict__ xt,    // x + t0*N + n
    float* __restrict__ op,          // out + t0*OUTW + n*16 + fg*8
    const float* __restrict__ sw,    // smem normalized weights [32][16]
    const float* __restrict__ sb,    // smem biases [16]
    int t0, int fg)
{
    // acc[t][q] = {out[t0+t, fg*8+2q], out[t0+t, fg*8+2q+1]} pre-relu
    ull acc[8][4];
    {
        const ull* sb2 = reinterpret_cast<const ull*>(sb) + fg * 4;
#pragma unroll
        for (int q = 0; q < 4; ++q) {
            ull b = sb2[q];
#pragma unroll
            for (int t = 0; t < 8; ++t) acc[t][q] = b;
        }
    }

    // weight rows as 16B chunks: row j = 4 x ulonglong2, this warp uses 2.
    const ulonglong2* wsrc = reinterpret_cast<const ulonglong2*>(sw) + fg * 2;

    // double-buffered weight pairs; wq[j&1] holds lag j's 4 filter-pairs
    ull wq[2][4];
    {
        ulonglong2 a = wsrc[0];
        ulonglong2 b = wsrc[1];
        wq[0][0] = a.x; wq[0][1] = a.y; wq[0][2] = b.x; wq[0][3] = b.y;
    }

    // Window entering group g (j0=4g): win[k] = x[t0 - 2*j0 - 7 + k], k=0..13.
    // Lag j0+d (d=0..3) needs rows win[6-2d .. 13-2d].
    float win[14];
#pragma unroll
    for (int k = 0; k < 14; ++k)
        win[k] = ldrow<GUARD>(xt, t0, -7 + k);

#pragma unroll
    for (int g = 0; g < 8; ++g) {
        // batch-prefetch next group's 8 rows (MLP=8, distance ~4 j-steps)
        float nbuf[8];
        if (g < 7) {
#pragma unroll
            for (int k = 0; k < 8; ++k)
                nbuf[k] = ldrow<GUARD>(xt, t0, -8 * g - 15 + k);
        }

#pragma unroll
        for (int d = 0; d < 4; ++d) {
            const int j   = 4 * g + d;
            const int cur = j & 1;
            const int nxt = cur ^ 1;

            // prefetch next lag's weights into the alternate buffer
            if (j < L_DIM - 1) {
                ulonglong2 a = wsrc[(j + 1) * 4];
                ulonglong2 b = wsrc[(j + 1) * 4 + 1];
                wq[nxt][0] = a.x; wq[nxt][1] = a.y;
                wq[nxt][2] = b.x; wq[nxt][3] = b.y;
            }

            ull xd[8];
#pragma unroll
            for (int t = 0; t < 8; ++t)
                xd[t] = dup2(win[6 - 2 * d + t]);

#pragma unroll
            for (int q = 0; q < 4; ++q) {
                ull w = wq[cur][q];
#pragma unroll
                for (int t = 0; t < 8; ++t)
                    fma2(acc[t][q], xd[t], w);
            }
        }

        // shift window down 8 rows; new base = old base - 8
        if (g < 7) {
#pragma unroll
            for (int k = 13; k >= 8; --k) win[k] = win[k - 8];
#pragma unroll
            for (int k = 0; k < 8; ++k) win[k] = nbuf[k];
        }
    }

    // relu + streaming stores: 8 contiguous floats per t = 2x STG.128.
    // Adjacent q-pairs are adjacent filters -> direct float4 assembly.
#pragma unroll
    for (int t = 0; t < 8; ++t) {
        float4* dst = reinterpret_cast<float4*>(op + (size_t)t * OUTW);
        float2 a0 = unpack2(acc[t][0]);
        float2 a1 = unpack2(acc[t][1]);
        float2 a2 = unpack2(acc[t][2]);
        float2 a3 = unpack2(acc[t][3]);
        float4 v0, v1;
        v0.x = fmaxf(a0.x, 0.0f); v0.y = fmaxf(a0.y, 0.0f);
        v0.z = fmaxf(a1.x, 0.0f); v0.w = fmaxf(a1.y, 0.0f);
        v1.x = fmaxf(a2.x, 0.0f); v1.y = fmaxf(a2.y, 0.0f);
        v1.z = fmaxf(a3.x, 0.0f); v1.w = fmaxf(a3.y, 0.0f);
        __stcs(dst + 0, v0);
        __stcs(dst + 1, v1);
    }
}

__global__ void __launch_bounds__(256, 2)
tlayer_kernel(const float* __restrict__ x,
              const float* __restrict__ W,
              const float* __restrict__ B,
              float* __restrict__ out)
{
    __shared__ __align__(16) float sw[L_DIM * F_DIM];  // normalized weights [j][f]
    __shared__ __align__(16) float sb[F_DIM];

    const int tid = threadIdx.x;

    // weight prep: relu + per-filter l2 normalize (matches reference)
    if (tid < F_DIM) {
        float ss = 0.0f;
        for (int j = 0; j < L_DIM; ++j) {
            float wv = fmaxf(__ldg(W + j * F_DIM + tid), 0.0f);
            ss += wv * wv;
        }
        float inv = rsqrtf(fmaxf(ss, 1e-12f));
        for (int j = 0; j < L_DIM; ++j) {
            sw[j * F_DIM + tid] = fmaxf(__ldg(W + j * F_DIM + tid), 0.0f) * inv;
        }
        sb[tid] = __ldg(B + tid);
    }
    __syncthreads();

    const int lane = tid & 31;
    const int warp = tid >> 5;
    const int tg   = warp >> 1;      // 4 t-groups of 8
    const int fg   = warp & 1;       // 2 filter-halves

    const int n  = blockIdx.x * 32 + lane;        // 128 n-blocks
    const int t0 = blockIdx.y * 32 + tg * 8;      // 64 t-blocks, 32 t per block

    const float* xt = x + (size_t)t0 * N_DIM + n;
    float*       op = out + (size_t)t0 * OUTW + (size_t)n * F_DIM + fg * 8;

    // deepest row touched is t0 - 63; guard only the first t-blocks
    if (t0 >= 63) {
        compute_tile<false>(xt, op, sw, sb, t0, fg);
    } else {
        compute_tile<true>(xt, op, sw, sb, t0, fg);
    }
}

extern "C" void kernel_launch(void* const* d_in, const int* in_sizes, int n_in,
                              void* d_out, int out_size) {
    (void)in_sizes; (void)n_in; (void)out_size;
    const float* x = (const float*)d_in[0];   // [2048, 4096]
    const float* W = (const float*)d_in[1];   // [32, 16]
    const float* B = (const float*)d_in[2];   // [16]
    float* out = (float*)d_out;               // [2048, 65536]

    dim3 grid(N_DIM / 32, T_DIM / 32);        // (128, 64)
    tlayer_kernel<<<grid, 256>>>(x, W, B, out);
}